// round 8
// baseline (speedup 1.0000x reference)
#include <cuda_runtime.h>
#include <cuda_fp16.h>

#define NN 100000
#define NE 1600000
#define CH 64
#define OUTC 32
#define NB 148
#define NT 1024
#define NWARPS (NB * (NT / 32))        // 4736
#define CHUNK 676                       // ceil(NN / NB); 148*676 = 100048
#define NR (NE + 3 * NN + 32)
#define SWS 68                          // padded W stride for 64-col layers

// ---------------- device scratch ----------------
__device__ int    g_deg[NN];
__device__ int    g_off[NN];
__device__ int    g_cur[NN];
__device__ float  g_dinv[NN];
__device__ int    g_bsums[NB];
__device__ __align__(16) int    g_r[NR];       // src rows, counting-sorted by target, 4-padded segs
__device__ __align__(16) __half g_t[NN * CH];  // dinv-scaled transformed features (fp16)
__device__ __align__(16) float  g_h[NN * CH];  // aggregated + relu (fp32)
__device__ unsigned g_cnt;                      // barrier arrival count (returns to 0)
__device__ unsigned g_gen;                      // barrier generation (monotonic across replays)

typedef unsigned long long u64;

__device__ __forceinline__ u64 pack2(float lo, float hi) {
    u64 r; asm("mov.b64 %0, {%1, %2};" : "=l"(r) : "f"(lo), "f"(hi)); return r;
}
__device__ __forceinline__ void unpack2(u64 v, float& lo, float& hi) {
    asm("mov.b64 {%0, %1}, %2;" : "=f"(lo), "=f"(hi) : "l"(v));
}
__device__ __forceinline__ void fma2(u64& acc, u64 a, u64 b) {
    asm("fma.rn.f32x2 %0, %1, %2, %0;" : "+l"(acc) : "l"(a), "l"(b));
}

// ---------------- shared ----------------
__shared__ __align__(16) float sW[CH * SWS];   // 17408 B, swizzled weight tile
__shared__ int      s_wsum[32];
__shared__ unsigned s_base;                    // barrier generation base
__shared__ int      s_prefix;                  // scan block base

// software grid barrier: all NB blocks co-resident by construction
__device__ __forceinline__ void gsync(unsigned target) {
    __threadfence();
    __syncthreads();
    if (threadIdx.x == 0) {
        if (atomicAdd(&g_cnt, 1u) == NB - 1) {
            atomicExch(&g_cnt, 0u);
            __threadfence();
            atomicExch(&g_gen, target);
        } else {
            while (atomicAdd(&g_gen, 0u) < target) { }
        }
    }
    __syncthreads();
}

// W swizzle: col c of a 64-wide k-row lives at k*SWS + c + 4*(c>>5)
__device__ __forceinline__ int wswz(int k, int c, int cols) {
    if (cols == 64) return k * SWS + c + 4 * (c >> 5);
    return k * OUTC + c;
}

// ---------------- GEMM phase: out[N, COUT] = X[N,64] @ W (+bias)(*dinv) ----------------
// 2 rows x 8 cols per thread; X register-staged float4; W in swizzled smem.
template<int COUT, bool BIAS, bool SCALE, bool HALFOUT>
__device__ void gemm_phase(const float* __restrict__ X, const float* __restrict__ W,
                           const float* __restrict__ bias, float* __restrict__ outp) {
    const int tid = threadIdx.x;
    for (int i = tid; i < CH * COUT; i += NT)
        sW[wswz(i / COUT, i % COUT, COUT)] = W[i];
    __syncthreads();

    constexpr int G   = COUT / 8;
    constexpr int RPB = (NT / G) * 2;
    const int cg = tid & (G - 1);
    const int rt = tid / G;
    const int ntiles = (NN + RPB - 1) / RPB;
    const int coff = (COUT == 64) ? (cg * 8 + 4 * (cg >> 2)) : (cg * 8);

    for (int tile = blockIdx.x; tile < ntiles; tile += NB) {
        int r0 = tile * RPB + rt * 2;
        int r1 = r0 + 1;
        bool a0 = r0 < NN, a1 = r1 < NN;
        const float4* x0p = (const float4*)(X + (size_t)r0 * CH);
        const float4* x1p = (const float4*)(X + (size_t)r1 * CH);
        u64 acc0[4] = {0, 0, 0, 0};
        u64 acc1[4] = {0, 0, 0, 0};
        const float4 fz = make_float4(0.f, 0.f, 0.f, 0.f);

#pragma unroll 2
        for (int kb = 0; kb < 16; kb++) {
            float4 xa = a0 ? x0p[kb] : fz;
            float4 xb = a1 ? x1p[kb] : fz;
            const float* pxa = (const float*)&xa;
            const float* pxb = (const float*)&xb;
#pragma unroll
            for (int j = 0; j < 4; j++) {
                int k = kb * 4 + j;
                int wrow = (COUT == 64) ? k * SWS : k * OUTC;
                u64 xp0 = pack2(pxa[j], pxa[j]);
                u64 xp1 = pack2(pxb[j], pxb[j]);
                ulonglong2 wa = *(const ulonglong2*)&sW[wrow + coff];
                ulonglong2 wb = *(const ulonglong2*)&sW[wrow + coff + 4];
                fma2(acc0[0], xp0, wa.x); fma2(acc0[1], xp0, wa.y);
                fma2(acc0[2], xp0, wb.x); fma2(acc0[3], xp0, wb.y);
                fma2(acc1[0], xp1, wa.x); fma2(acc1[1], xp1, wa.y);
                fma2(acc1[2], xp1, wb.x); fma2(acc1[3], xp1, wb.y);
            }
        }

        float4 bb0 = make_float4(0, 0, 0, 0), bb1 = make_float4(0, 0, 0, 0);
        if (BIAS) {
            bb0 = *(const float4*)&bias[cg * 8];
            bb1 = *(const float4*)&bias[cg * 8 + 4];
        }
#pragma unroll
        for (int p = 0; p < 2; p++) {
            int row = (p == 0) ? r0 : r1;
            if (row < NN) {
                u64* acc = (p == 0) ? acc0 : acc1;
                float4 f0, f1;
                unpack2(acc[0], f0.x, f0.y); unpack2(acc[1], f0.z, f0.w);
                unpack2(acc[2], f1.x, f1.y); unpack2(acc[3], f1.z, f1.w);
                if (SCALE) {
                    float s = g_dinv[row];
                    f0.x *= s; f0.y *= s; f0.z *= s; f0.w *= s;
                    f1.x *= s; f1.y *= s; f1.z *= s; f1.w *= s;
                }
                if (BIAS) {
                    f0.x += bb0.x; f0.y += bb0.y; f0.z += bb0.z; f0.w += bb0.w;
                    f1.x += bb1.x; f1.y += bb1.y; f1.z += bb1.z; f1.w += bb1.w;
                }
                if (HALFOUT) {
                    __half2 hv[4];
                    hv[0] = __floats2half2_rn(f0.x, f0.y);
                    hv[1] = __floats2half2_rn(f0.z, f0.w);
                    hv[2] = __floats2half2_rn(f1.x, f1.y);
                    hv[3] = __floats2half2_rn(f1.z, f1.w);
                    *(uint4*)&g_t[(size_t)row * COUT + cg * 8] = *(uint4*)hv;
                } else {
                    *(float4*)&outp[(size_t)row * COUT + cg * 8]     = f0;
                    *(float4*)&outp[(size_t)row * COUT + cg * 8 + 4] = f1;
                }
            }
        }
    }
    __syncthreads();   // protect sW before any later phase reload
}

// ---------------- agg phase: g_h[t] = relu(dinv[t]*(sum_nbr ts[r] + ts[t]) + b) --------
__device__ void agg_phase(const float* __restrict__ bias) {
    const int lane = threadIdx.x & 31;
    const int gw0  = blockIdx.x * (NT / 32) + (threadIdx.x >> 5);
    const __half2* hp = (const __half2*)g_t;
    for (int node = gw0; node < NN; node += NWARPS) {
        int start = g_off[node];
        int cnt   = g_deg[node];
        float ax = 0.f, ay = 0.f;
        int endt = start + cnt;
        for (int e = start; e < endt; e += 8) {
            int4 a = *(const int4*)&g_r[e];
            int4 b = *(const int4*)&g_r[e + 4];
            int rem = endt - e;
            {            float2 v = __half22float2(hp[a.x * 32 + lane]); ax += v.x; ay += v.y; }
            if (rem > 1) { float2 v = __half22float2(hp[a.y * 32 + lane]); ax += v.x; ay += v.y; }
            if (rem > 2) { float2 v = __half22float2(hp[a.z * 32 + lane]); ax += v.x; ay += v.y; }
            if (rem > 3) { float2 v = __half22float2(hp[a.w * 32 + lane]); ax += v.x; ay += v.y; }
            if (rem > 4) { float2 v = __half22float2(hp[b.x * 32 + lane]); ax += v.x; ay += v.y; }
            if (rem > 5) { float2 v = __half22float2(hp[b.y * 32 + lane]); ax += v.x; ay += v.y; }
            if (rem > 6) { float2 v = __half22float2(hp[b.z * 32 + lane]); ax += v.x; ay += v.y; }
            if (rem > 7) { float2 v = __half22float2(hp[b.w * 32 + lane]); ax += v.x; ay += v.y; }
        }
        float dt = g_dinv[node];
        float2 sv = __half22float2(hp[node * 32 + lane]);
        float2 bb = ((const float2*)bias)[lane];
        float ox = fmaf(dt, ax + sv.x, bb.x);
        float oy = fmaf(dt, ay + sv.y, bb.y);
        ((float2*)g_h)[node * 32 + lane] = make_float2(fmaxf(ox, 0.f), fmaxf(oy, 0.f));
    }
}

// ---------------- the persistent mega-kernel ----------------
extern "C" __global__ void __launch_bounds__(NT, 1)
mega(const float* __restrict__ x, const int* __restrict__ ei,
     const float* __restrict__ W1, const float* __restrict__ b1,
     const float* __restrict__ W2, const float* __restrict__ b2,
     const float* __restrict__ Wlin, const float* __restrict__ blin,
     float* __restrict__ out) {
    const int tid = threadIdx.x;
    const int bid = blockIdx.x;
    const int gt  = bid * NT + tid;
    const int GS  = NB * NT;

    if (tid == 0) s_base = atomicAdd(&g_gen, 0u);
    __syncthreads();
    const unsigned base = s_base;

    // ---- P0: zero degrees + GEMM1 (CSR-independent; unscaled fp16 -> g_t) ----
    for (int i = gt; i < NN; i += GS) g_deg[i] = 0;
    gsync(base + 1);                     // zero must complete before count atomics
    // note: gemm1 placed after the zero-barrier would serialize; instead run it now,
    // overlapped with nothing it conflicts with (g_t untouched by CSR build)
    gemm_phase<CH, false, false, true>(x, W1, nullptr, nullptr);

    // ---- P1: degree count ----
    for (int e4 = gt; e4 < NE / 4; e4 += GS) {
        int4 c = *(const int4*)&ei[NE + e4 * 4];
        atomicAdd(&g_deg[c.x], 1);
        atomicAdd(&g_deg[c.y], 1);
        atomicAdd(&g_deg[c.z], 1);
        atomicAdd(&g_deg[c.w], 1);
    }
    gsync(base + 2);

    // ---- P2: per-block scan of padded degrees over contiguous chunk ----
    {
        int node = bid * CHUNK + tid;
        int deg  = (tid < CHUNK && node < NN) ? g_deg[node] : 0;
        int v    = (deg + 3) & ~3;
        int lane = tid & 31, wid = tid >> 5;
        int s = v;
#pragma unroll
        for (int d = 1; d < 32; d <<= 1) {
            int n = __shfl_up_sync(0xffffffffu, s, d);
            if (lane >= d) s += n;
        }
        if (lane == 31) s_wsum[wid] = s;
        __syncthreads();
        if (wid == 0) {
            int t = s_wsum[lane];
#pragma unroll
            for (int d = 1; d < 32; d <<= 1) {
                int n = __shfl_up_sync(0xffffffffu, t, d);
                if (lane >= d) t += n;
            }
            s_wsum[lane] = t;
        }
        __syncthreads();
        int warpExcl = (wid > 0) ? s_wsum[wid - 1] : 0;
        if (tid < CHUNK && node < NN) g_off[node] = warpExcl + (s - v);
        if (tid == 0) g_bsums[bid] = s_wsum[31];
        gsync(base + 3);

        // ---- P3: block base prefix + finalize offsets/cursors/dinv ----
        if (tid < 32) {
            int sum = 0;
            for (int j = tid; j < bid; j += 32) sum += g_bsums[j];
#pragma unroll
            for (int d = 16; d; d >>= 1) sum += __shfl_xor_sync(0xffffffffu, sum, d);
            if (tid == 0) s_prefix = sum;
        }
        __syncthreads();
        if (tid < CHUNK && node < NN) {
            int o = g_off[node] + s_prefix;
            g_off[node] = o;
            g_cur[node] = o;
            g_dinv[node] = rsqrtf((float)(deg + 1));
        }
    }
    gsync(base + 4);

    // ---- P4: fill CSR + scale g_t rows by dinv ----
    for (int e4 = gt; e4 < NE / 4; e4 += GS) {
        int4 r = *(const int4*)&ei[e4 * 4];
        int4 c = *(const int4*)&ei[NE + e4 * 4];
        g_r[atomicAdd(&g_cur[c.x], 1)] = r.x;
        g_r[atomicAdd(&g_cur[c.y], 1)] = r.y;
        g_r[atomicAdd(&g_cur[c.z], 1)] = r.z;
        g_r[atomicAdd(&g_cur[c.w], 1)] = r.w;
    }
    {   // scale: g_t[row][*] *= dinv[row]   (half2 granularity, 32 per row)
        __half2* hp = (__half2*)g_t;
        for (int i = gt; i < NN * 32; i += GS) {
            float s = g_dinv[i >> 5];
            float2 f = __half22float2(hp[i]);
            hp[i] = __floats2half2_rn(f.x * s, f.y * s);
        }
    }
    gsync(base + 5);

    // ---- P5: agg layer 1 ----
    agg_phase(b1);
    gsync(base + 6);

    // ---- P6: GEMM2 (scaled fp16 -> g_t) ----
    gemm_phase<CH, false, true, true>(g_h, W2, nullptr, nullptr);
    gsync(base + 7);

    // ---- P7: agg layer 2 ----
    agg_phase(b2);
    gsync(base + 8);

    // ---- P8: linear head -> out (fp32 + bias) ----
    gemm_phase<OUTC, true, false, false>(g_h, Wlin, blin, out);
}

// ---------------- launch ----------------
extern "C" void kernel_launch(void* const* d_in, const int* in_sizes, int n_in,
                              void* d_out, int out_size) {
    const float* x    = (const float*)d_in[0];
    const int*   ei   = (const int*)d_in[1];
    const float* W1   = (const float*)d_in[2];
    const float* b1   = (const float*)d_in[3];
    const float* W2   = (const float*)d_in[4];
    const float* b2   = (const float*)d_in[5];
    const float* Wlin = (const float*)d_in[6];
    const float* blin = (const float*)d_in[7];
    float* out = (float*)d_out;

    mega<<<NB, NT>>>(x, ei, W1, b1, W2, b2, Wlin, blin, out);
}